// round 11
// baseline (speedup 1.0000x reference)
#include <cuda_runtime.h>
#include <cuda_bf16.h>
#include <math.h>
#include <stdint.h>

using bf16 = __nv_bfloat16;

// ================= device scratch (no allocations allowed) =================
__device__ bf16 g_xh[3UL * 8192 * 512],  g_xl[3UL * 8192 * 512];
__device__ bf16 g_wth[3UL * 4096 * 512], g_wtl[3UL * 4096 * 512]; // W^T x3 / Wo^T (slice 0)
__device__ bf16 g_qh[8192UL * 4096], g_ql[8192UL * 4096];
__device__ bf16 g_kh[8192UL * 4096], g_kl[8192UL * 4096];
__device__ bf16 g_vh[8192UL * 4096], g_vl[8192UL * 4096];
__device__ bf16 g_vth[64UL * 512 * 1024], g_vtl[64UL * 512 * 1024];
__device__ bf16 g_ph[64UL * 1024 * 1024], g_pl[64UL * 1024 * 1024];
__device__ bf16 g_ch[8192UL * 4096], g_cl[8192UL * 4096];
__device__ float g_attn_fb[64UL * 1024 * 1024];

// ================= helpers =================
__device__ __forceinline__ uint32_t smem_u32(const void* p) {
    return (uint32_t)__cvta_generic_to_shared(p);
}
__device__ __forceinline__ void ldsm4(uint32_t* r, uint32_t a) {
    asm volatile("ldmatrix.sync.aligned.m8n8.x4.shared.b16 {%0,%1,%2,%3},[%4];\n"
        : "=r"(r[0]), "=r"(r[1]), "=r"(r[2]), "=r"(r[3]) : "r"(a));
}
__device__ __forceinline__ void mma_bf16(float* d, const uint32_t* a, const uint32_t* b) {
    asm("mma.sync.aligned.m16n8k16.row.col.f32.bf16.bf16.f32 "
        "{%0,%1,%2,%3},{%4,%5,%6,%7},{%8,%9},{%0,%1,%2,%3};\n"
        : "+f"(d[0]), "+f"(d[1]), "+f"(d[2]), "+f"(d[3])
        : "r"(a[0]), "r"(a[1]), "r"(a[2]), "r"(a[3]), "r"(b[0]), "r"(b[1]));
}
__device__ __forceinline__ void cpasync16(uint32_t dst, const void* src) {
    asm volatile("cp.async.cg.shared.global [%0], [%1], 16;" :: "r"(dst), "l"(src));
}
#define CP_COMMIT() asm volatile("cp.async.commit_group;" ::: "memory")
#define CP_WAIT1()  asm volatile("cp.async.wait_group 1;" ::: "memory")

__device__ __forceinline__ void split_bf16(float x, bf16& h, bf16& l) {
    h = __float2bfloat16(x);
    l = __float2bfloat16(x - __bfloat162float(h));
}

// ================= bf16x3 cp.async pipelined GEMM =================
// Block tile 128(M) x 256(N) x 32(K); 8 warps of 64x64; 2-stage pipeline.
// Stage layout: Ah[128*80] Al[128*80] Bh[256*80] Bl[256*80] = 61440 B.
#define STAGE_BYTES 61440
#define SMEM_GEMM   122880

__device__ __forceinline__ void load_stage(
    uint32_t sbase, const bf16* __restrict__ Ah, const bf16* __restrict__ Al, int lda,
    const bf16* __restrict__ Bh, const bf16* __restrict__ Bl, int ldb,
    int m0, int n0, int k0)
{
    const int tid = threadIdx.x;
    // A: 128 rows x 4 chunks = 512 -> 2 per thread (hi+lo)
#pragma unroll
    for (int i = 0; i < 2; i++) {
        const int chunk = tid + i * 256;
        const int row = chunk >> 2;
        const int cb  = (chunk & 3) * 16;
        const int ce  = (chunk & 3) * 8;
        const uint32_t so = sbase + row * 80 + cb;
        cpasync16(so,          Ah + (size_t)(m0 + row) * lda + k0 + ce);
        cpasync16(so + 10240,  Al + (size_t)(m0 + row) * lda + k0 + ce);
    }
    // B: 256 rows x 4 chunks = 1024 -> 4 per thread (hi+lo)
#pragma unroll
    for (int i = 0; i < 4; i++) {
        const int chunk = tid + i * 256;
        const int row = chunk >> 2;
        const int cb  = (chunk & 3) * 16;
        const int ce  = (chunk & 3) * 8;
        const uint32_t so = sbase + 20480 + row * 80 + cb;
        cpasync16(so,          Bh + (size_t)(n0 + row) * ldb + k0 + ce);
        cpasync16(so + 20480,  Bl + (size_t)(n0 + row) * ldb + k0 + ce);
    }
}

template <int OUTMODE /*0=f32, 1=bf16 hi/lo*/, bool BIAS>
__device__ __forceinline__ void gemm_core(
    const bf16* __restrict__ Ah, const bf16* __restrict__ Al, int lda,
    const bf16* __restrict__ Bh, const bf16* __restrict__ Bl, int ldb,
    float* __restrict__ C, bf16* __restrict__ Ch, bf16* __restrict__ Cl, int ldc,
    int K, const float* __restrict__ bias)
{
    extern __shared__ char smem[];
    const uint32_t sb = smem_u32(smem);
    const int tid = threadIdx.x, lane = tid & 31, warp = tid >> 5;
    const int wm = warp >> 2, wn = warp & 3;          // 2 x 4 warp grid, 64x64 tiles
    const int m0 = blockIdx.y * 128, n0 = blockIdx.x * 256;

    float acc[4][8][4] = {};   // [m16][n8][regs]

    load_stage(sb,               Ah, Al, lda, Bh, Bl, ldb, m0, n0, 0);
    CP_COMMIT();
    load_stage(sb + STAGE_BYTES, Ah, Al, lda, Bh, Bl, ldb, m0, n0, 32);
    CP_COMMIT();

    const int T = K >> 5;
    const int offA = (lane & 15) * 80 + (lane >> 4) * 16;
    const int offB = (((lane >> 4) & 1) * 8 + (lane & 7)) * 80 + ((lane >> 3) & 1) * 16;

    for (int t = 0; t < T; t++) {
        CP_WAIT1();
        __syncthreads();
        const uint32_t st = sb + (t & 1) * STAGE_BYTES;
        const uint32_t baseAh = st + wm * 64 * 80 + offA;
        const uint32_t baseAl = baseAh + 10240;
        const uint32_t baseBh = st + 20480 + wn * 64 * 80 + offB;
        const uint32_t baseBl = baseBh + 20480;

#pragma unroll
        for (int ks = 0; ks < 2; ks++) {
            uint32_t bh[4][4], bl[4][4], af[4][4];
#pragma unroll
            for (int j = 0; j < 4; j++) {
                ldsm4(bh[j], baseBh + j * 16 * 80 + ks * 32);
                ldsm4(bl[j], baseBl + j * 16 * 80 + ks * 32);
            }
#pragma unroll
            for (int mi = 0; mi < 4; mi++)
                ldsm4(af[mi], baseAh + mi * 16 * 80 + ks * 32);

            // sweep 1: hi*hi
#pragma unroll
            for (int mi = 0; mi < 4; mi++)
#pragma unroll
                for (int ni = 0; ni < 8; ni++)
                    mma_bf16(acc[mi][ni], af[mi], &bh[ni >> 1][(ni & 1) * 2]);
            // sweep 2: hi*lo
#pragma unroll
            for (int mi = 0; mi < 4; mi++)
#pragma unroll
                for (int ni = 0; ni < 8; ni++)
                    mma_bf16(acc[mi][ni], af[mi], &bl[ni >> 1][(ni & 1) * 2]);
            // reload A-lo into same frags; sweep 3: lo*hi
#pragma unroll
            for (int mi = 0; mi < 4; mi++)
                ldsm4(af[mi], baseAl + mi * 16 * 80 + ks * 32);
#pragma unroll
            for (int mi = 0; mi < 4; mi++)
#pragma unroll
                for (int ni = 0; ni < 8; ni++)
                    mma_bf16(acc[mi][ni], af[mi], &bh[ni >> 1][(ni & 1) * 2]);
        }
        __syncthreads();
        if (t + 2 < T)
            load_stage(sb + (t & 1) * STAGE_BYTES, Ah, Al, lda, Bh, Bl, ldb,
                       m0, n0, (t + 2) * 32);
        CP_COMMIT();
    }

    const int mw = m0 + wm * 64, nw = n0 + wn * 64;
#pragma unroll
    for (int mi = 0; mi < 4; mi++) {
        const int r0 = mw + mi * 16 + (lane >> 2);
#pragma unroll
        for (int ni = 0; ni < 8; ni++) {
            const int c = nw + ni * 8 + (lane & 3) * 2;
            float v0 = acc[mi][ni][0], v1 = acc[mi][ni][1];
            float v2 = acc[mi][ni][2], v3 = acc[mi][ni][3];
            if (BIAS) {
                float2 bb = *reinterpret_cast<const float2*>(&bias[c]);
                v0 += bb.x; v1 += bb.y; v2 += bb.x; v3 += bb.y;
            }
            if (OUTMODE == 0) {
                float2 o0; o0.x = v0; o0.y = v1;
                float2 o1; o1.x = v2; o1.y = v3;
                *reinterpret_cast<float2*>(&C[(size_t)r0 * ldc + c]) = o0;
                *reinterpret_cast<float2*>(&C[(size_t)(r0 + 8) * ldc + c]) = o1;
            } else {
                bf16 h, l;
                __nv_bfloat162 hh, ll;
                split_bf16(v0, h, l); hh.x = h; ll.x = l;
                split_bf16(v1, h, l); hh.y = h; ll.y = l;
                *reinterpret_cast<__nv_bfloat162*>(&Ch[(size_t)r0 * ldc + c]) = hh;
                *reinterpret_cast<__nv_bfloat162*>(&Cl[(size_t)r0 * ldc + c]) = ll;
                split_bf16(v2, h, l); hh.x = h; ll.x = l;
                split_bf16(v3, h, l); hh.y = h; ll.y = l;
                *reinterpret_cast<__nv_bfloat162*>(&Ch[(size_t)(r0 + 8) * ldc + c]) = hh;
                *reinterpret_cast<__nv_bfloat162*>(&Cl[(size_t)(r0 + 8) * ldc + c]) = ll;
            }
        }
    }
}

// ---------------- GEMM wrappers ----------------
__global__ __launch_bounds__(256, 1) void gemm_proj3_kernel(
    const bf16* xh, const bf16* xl, const bf16* wth, const bf16* wtl,
    bf16* qh, bf16* ql, bf16* kh, bf16* kl, bf16* vh, bf16* vl,
    const float* bq, const float* bk, const float* bv)
{
    const int z = blockIdx.z;
    const size_t xo = (size_t)z * 8192 * 512;
    const size_t wo_ = (size_t)z * 4096 * 512;
    bf16* Ch = (z == 0) ? qh : (z == 1) ? kh : vh;
    bf16* Cl = (z == 0) ? ql : (z == 1) ? kl : vl;
    const float* bias = (z == 0) ? bq : (z == 1) ? bk : bv;
    gemm_core<1, true>(xh + xo, xl + xo, 512, wth + wo_, wtl + wo_, 512,
                       nullptr, Ch, Cl, 4096, 512, bias);
}

__global__ __launch_bounds__(256, 1) void gemm_qk_kernel(
    const bf16* Qh, const bf16* Ql, const bf16* Kh, const bf16* Kl, float* logits)
{
    const int z = blockIdx.z, b = z >> 3, h = z & 7;
    const size_t ao = (size_t)b * 1024 * 4096 + (size_t)h * 512;
    gemm_core<0, false>(Qh + ao, Ql + ao, 4096, Kh + ao, Kl + ao, 4096,
                        logits + ((size_t)z << 20), nullptr, nullptr, 1024, 512, nullptr);
}

__global__ __launch_bounds__(256, 1) void gemm_av_kernel(
    const bf16* Ph, const bf16* Pl, const bf16* VTh, const bf16* VTl,
    bf16* Ch, bf16* Cl)
{
    const int z = blockIdx.z, b = z >> 3, h = z & 7;
    const size_t po = (size_t)z << 20;
    const size_t vo = (size_t)z * 512 * 1024;
    const size_t co = (size_t)b * 1024 * 4096 + (size_t)h * 512;
    gemm_core<1, false>(Ph + po, Pl + po, 1024, VTh + vo, VTl + vo, 1024,
                        nullptr, Ch + co, Cl + co, 4096, 1024, nullptr);
}

__global__ __launch_bounds__(256, 1) void gemm_wo_kernel(
    const bf16* Ah, const bf16* Al, const bf16* Wth, const bf16* Wtl,
    float* out, const float* bo)
{
    gemm_core<0, true>(Ah, Al, 4096, Wth, Wtl, 4096, out, nullptr, nullptr, 512, 4096, bo);
}

// ---------------- prep kernels ----------------
__global__ __launch_bounds__(256) void split3_kernel(
    const float* __restrict__ q_ip, const float* __restrict__ k_ip,
    const float* __restrict__ v_ip, bf16* __restrict__ xh, bf16* __restrict__ xl)
{
    const int z = blockIdx.y;
    const float* src = (z == 0) ? q_ip : (z == 1) ? k_ip : v_ip;
    bf16* dh = xh + (size_t)z * 8192 * 512;
    bf16* dl = xl + (size_t)z * 8192 * 512;
    const int base = blockIdx.x * 1024 + threadIdx.x;

    float4 v[4];
#pragma unroll
    for (int j = 0; j < 4; j++)
        v[j] = reinterpret_cast<const float4*>(src)[base + j * 256];
#pragma unroll
    for (int j = 0; j < 4; j++) {
        const int i = base + j * 256;
        bf16 h0, l0, h1, l1, h2, l2, h3, l3;
        split_bf16(v[j].x, h0, l0); split_bf16(v[j].y, h1, l1);
        split_bf16(v[j].z, h2, l2); split_bf16(v[j].w, h3, l3);
        __nv_bfloat162 a, b2;
        a.x = h0; a.y = h1; b2.x = h2; b2.y = h3;
        reinterpret_cast<__nv_bfloat162*>(dh)[2 * i]     = a;
        reinterpret_cast<__nv_bfloat162*>(dh)[2 * i + 1] = b2;
        a.x = l0; a.y = l1; b2.x = l2; b2.y = l3;
        reinterpret_cast<__nv_bfloat162*>(dl)[2 * i]     = a;
        reinterpret_cast<__nv_bfloat162*>(dl)[2 * i + 1] = b2;
    }
}

__global__ __launch_bounds__(256) void tsplit_kernel(
    const float* __restrict__ src, bf16* __restrict__ th, bf16* __restrict__ tl,
    int R0, int C0)
{
    __shared__ float tile[32][33];
    const int c0 = blockIdx.x * 32, r0 = blockIdx.y * 32;
    const int tx = threadIdx.x & 31, ty0 = threadIdx.x >> 5;
#pragma unroll
    for (int j = 0; j < 4; j++) {
        const int ty = ty0 * 4 + j;
        tile[ty][tx] = src[(size_t)(r0 + ty) * C0 + c0 + tx];
    }
    __syncthreads();
#pragma unroll
    for (int j = 0; j < 4; j++) {
        const int ty = ty0 * 4 + j;
        float v = tile[tx][ty];
        bf16 h, l; split_bf16(v, h, l);
        th[(size_t)(c0 + ty) * R0 + r0 + tx] = h;
        tl[(size_t)(c0 + ty) * R0 + r0 + tx] = l;
    }
}

__global__ __launch_bounds__(256) void tsplit3_kernel(
    const float* __restrict__ wq, const float* __restrict__ wk,
    const float* __restrict__ wv, bf16* __restrict__ wth, bf16* __restrict__ wtl)
{
    const int z = blockIdx.z;
    const float* src = (z == 0) ? wq : (z == 1) ? wk : wv;
    bf16* th = wth + (size_t)z * 4096 * 512;
    bf16* tl = wtl + (size_t)z * 4096 * 512;
    __shared__ float tile[32][33];
    const int c0 = blockIdx.x * 32, r0 = blockIdx.y * 32;
    const int tx = threadIdx.x & 31, ty0 = threadIdx.x >> 5;
#pragma unroll
    for (int j = 0; j < 4; j++) {
        const int ty = ty0 * 4 + j;
        tile[ty][tx] = src[(size_t)(r0 + ty) * 4096 + c0 + tx];
    }
    __syncthreads();
#pragma unroll
    for (int j = 0; j < 4; j++) {
        const int ty = ty0 * 4 + j;
        float v = tile[tx][ty];
        bf16 h, l; split_bf16(v, h, l);
        th[(size_t)(c0 + ty) * 512 + r0 + tx] = h;
        tl[(size_t)(c0 + ty) * 512 + r0 + tx] = l;
    }
}

__global__ __launch_bounds__(256) void vtrans_kernel(
    const bf16* __restrict__ Vh, const bf16* __restrict__ Vl,
    bf16* __restrict__ VTh, bf16* __restrict__ VTl)
{
    const int z = blockIdx.z, b = z >> 3, h = z & 7;
    const int s0 = blockIdx.x * 32, d0 = blockIdx.y * 32;
    __shared__ bf16 th[32][33], tl2[32][33];
    const int tx = threadIdx.x & 31, ty0 = threadIdx.x >> 5;
    const size_t srcb = (size_t)(b * 1024) * 4096 + (size_t)h * 512;
#pragma unroll
    for (int j = 0; j < 4; j++) {
        const int ty = ty0 * 4 + j;
        th[ty][tx]  = Vh[srcb + (size_t)(s0 + ty) * 4096 + d0 + tx];
        tl2[ty][tx] = Vl[srcb + (size_t)(s0 + ty) * 4096 + d0 + tx];
    }
    __syncthreads();
    const size_t dstb = (size_t)z * 512 * 1024;
#pragma unroll
    for (int j = 0; j < 4; j++) {
        const int ty = ty0 * 4 + j;
        VTh[dstb + (size_t)(d0 + ty) * 1024 + s0 + tx] = th[tx][ty];
        VTl[dstb + (size_t)(d0 + ty) * 1024 + s0 + tx] = tl2[tx][ty];
    }
}

// ---------------- masked softmax: warp-per-row ----------------
__global__ __launch_bounds__(256) void softmax_kernel(
    float* __restrict__ attn, const float* __restrict__ mask,
    bf16* __restrict__ Ph, bf16* __restrict__ Pl)
{
    const int wid = threadIdx.x >> 5, lane = threadIdx.x & 31;
    const int r = blockIdx.x * 8 + wid;
    const int q = r & 1023;
    const int b = r >> 13;
    float* row = attn + (size_t)r * 1024;
    const float* mrow = mask + ((size_t)b * 1024 + q) * 1024;
    const float scale = 0.044194173824159216f;

    float4 v[8];
#pragma unroll
    for (int j = 0; j < 8; j++) {
        const int c4 = lane + j * 32;
        float4 lg = *reinterpret_cast<const float4*>(&row[c4 * 4]);
        float4 mk = *reinterpret_cast<const float4*>(&mrow[c4 * 4]);
        v[j].x = lg.x * scale + mk.x * (-1e9f);
        v[j].y = lg.y * scale + mk.y * (-1e9f);
        v[j].z = lg.z * scale + mk.z * (-1e9f);
        v[j].w = lg.w * scale + mk.w * (-1e9f);
    }

    float mx = -INFINITY;
#pragma unroll
    for (int j = 0; j < 8; j++)
        mx = fmaxf(mx, fmaxf(fmaxf(v[j].x, v[j].y), fmaxf(v[j].z, v[j].w)));
#pragma unroll
    for (int o = 16; o > 0; o >>= 1)
        mx = fmaxf(mx, __shfl_xor_sync(0xffffffffu, mx, o));

    float s = 0.f;
#pragma unroll
    for (int j = 0; j < 8; j++) {
        v[j].x = __expf(v[j].x - mx); v[j].y = __expf(v[j].y - mx);
        v[j].z = __expf(v[j].z - mx); v[j].w = __expf(v[j].w - mx);
        s += (v[j].x + v[j].y) + (v[j].z + v[j].w);
    }
#pragma unroll
    for (int o = 16; o > 0; o >>= 1)
        s += __shfl_xor_sync(0xffffffffu, s, o);
    const float inv = 1.0f / s;

    const size_t pbase = (size_t)r * 1024;
#pragma unroll
    for (int j = 0; j < 8; j++) {
        const int c4 = lane + j * 32;
        v[j].x *= inv; v[j].y *= inv; v[j].z *= inv; v[j].w *= inv;
        *reinterpret_cast<float4*>(&row[c4 * 4]) = v[j];

        bf16 h0, l0, h1, l1, h2, l2, h3, l3;
        split_bf16(v[j].x, h0, l0); split_bf16(v[j].y, h1, l1);
        split_bf16(v[j].z, h2, l2); split_bf16(v[j].w, h3, l3);
        __nv_bfloat162 hv[2], lv[2];
        hv[0].x = h0; hv[0].y = h1; hv[1].x = h2; hv[1].y = h3;
        lv[0].x = l0; lv[0].y = l1; lv[1].x = l2; lv[1].y = l3;
        *reinterpret_cast<uint2*>(&Ph[pbase + c4 * 4]) = *reinterpret_cast<uint2*>(hv);
        *reinterpret_cast<uint2*>(&Pl[pbase + c4 * 4]) = *reinterpret_cast<uint2*>(lv);
    }
}

// ===========================================================================
extern "C" void kernel_launch(void* const* d_in, const int* in_sizes, int n_in,
                              void* d_out, int out_size)
{
    const float* v_ip = (const float*)d_in[0];
    const float* k_ip = (const float*)d_in[1];
    const float* q_ip = (const float*)d_in[2];
    const float* mask = (const float*)d_in[3];
    const float* wq   = (const float*)d_in[4];
    const float* bq   = (const float*)d_in[5];
    const float* wk   = (const float*)d_in[6];
    const float* bk   = (const float*)d_in[7];
    const float* wv   = (const float*)d_in[8];
    const float* bv   = (const float*)d_in[9];
    const float* wo   = (const float*)d_in[10];
    const float* bo   = (const float*)d_in[11];

    bf16 *xh, *xl, *wth, *wtl, *qh, *ql, *kh, *kl, *vh, *vl, *vth, *vtl, *ph, *pl, *ch, *cl;
    float* fb;
    cudaGetSymbolAddress((void**)&xh, g_xh);   cudaGetSymbolAddress((void**)&xl, g_xl);
    cudaGetSymbolAddress((void**)&wth, g_wth); cudaGetSymbolAddress((void**)&wtl, g_wtl);
    cudaGetSymbolAddress((void**)&qh, g_qh);   cudaGetSymbolAddress((void**)&ql, g_ql);
    cudaGetSymbolAddress((void**)&kh, g_kh);   cudaGetSymbolAddress((void**)&kl, g_kl);
    cudaGetSymbolAddress((void**)&vh, g_vh);   cudaGetSymbolAddress((void**)&vl, g_vl);
    cudaGetSymbolAddress((void**)&vth, g_vth); cudaGetSymbolAddress((void**)&vtl, g_vtl);
    cudaGetSymbolAddress((void**)&ph, g_ph);   cudaGetSymbolAddress((void**)&pl, g_pl);
    cudaGetSymbolAddress((void**)&ch, g_ch);   cudaGetSymbolAddress((void**)&cl, g_cl);
    cudaGetSymbolAddress((void**)&fb, g_attn_fb);

    cudaFuncSetAttribute(gemm_proj3_kernel, cudaFuncAttributeMaxDynamicSharedMemorySize, SMEM_GEMM);
    cudaFuncSetAttribute(gemm_qk_kernel,    cudaFuncAttributeMaxDynamicSharedMemorySize, SMEM_GEMM);
    cudaFuncSetAttribute(gemm_av_kernel,    cudaFuncAttributeMaxDynamicSharedMemorySize, SMEM_GEMM);
    cudaFuncSetAttribute(gemm_wo_kernel,    cudaFuncAttributeMaxDynamicSharedMemorySize, SMEM_GEMM);

    const size_t OUT_ELEMS  = 8UL * 1024 * 512;
    const size_t ATTN_ELEMS = 64UL * 1024 * 1024;
    float* out  = (float*)d_out;
    float* attn = ((size_t)out_size >= OUT_ELEMS + ATTN_ELEMS) ? (out + OUT_ELEMS) : fb;

    // 1) prep
    split3_kernel<<<dim3(1024, 3), 256>>>(q_ip, k_ip, v_ip, xh, xl);
    tsplit3_kernel<<<dim3(128, 16, 3), 256>>>(wq, wk, wv, wth, wtl);

    // 2) Q/K/V projections (N=4096 -> 16 tiles of 256)
    gemm_proj3_kernel<<<dim3(16, 64, 3), 256, SMEM_GEMM>>>(
        xh, xl, wth, wtl, qh, ql, kh, kl, vh, vl, bq, bk, bv);

    // 3) V^T per (b,h)
    vtrans_kernel<<<dim3(32, 16, 64), 256>>>(vh, vl, vth, vtl);

    // 4) logits = Q K^T (N=1024 -> 4 tiles)
    gemm_qk_kernel<<<dim3(4, 8, 64), 256, SMEM_GEMM>>>(qh, ql, kh, kl, attn);

    // 5) masked softmax -> attn fp32 + P bf16 hi/lo
    softmax_kernel<<<8192, 256>>>(attn, mask, ph, pl);

    // 6) ctx = P @ V (N=512 -> 2 tiles)
    gemm_av_kernel<<<dim3(2, 8, 64), 256, SMEM_GEMM>>>(ph, pl, vth, vtl, ch, cl);

    // 7) out = ctx @ wo + bo (N=512 -> 2 tiles)
    tsplit_kernel<<<dim3(16, 128), 256>>>(wo, wth, wtl, 4096, 512);
    gemm_wo_kernel<<<dim3(2, 64), 256, SMEM_GEMM>>>(ch, cl, wth, wtl, out, bo);
}

// round 14
// speedup vs baseline: 1.1022x; 1.1022x over previous
#include <cuda_runtime.h>
#include <cuda_bf16.h>
#include <math.h>
#include <stdint.h>

using bf16 = __nv_bfloat16;

// ================= device scratch (no allocations allowed) =================
__device__ bf16 g_xh[3UL * 8192 * 512],  g_xl[3UL * 8192 * 512];
__device__ bf16 g_wth[3UL * 4096 * 512], g_wtl[3UL * 4096 * 512]; // W^T x3 / Wo^T (slice 0)
__device__ bf16 g_qh[8192UL * 4096], g_ql[8192UL * 4096];
__device__ bf16 g_kh[8192UL * 4096], g_kl[8192UL * 4096];
__device__ bf16 g_vh[8192UL * 4096], g_vl[8192UL * 4096];
__device__ bf16 g_vth[64UL * 512 * 1024], g_vtl[64UL * 512 * 1024];
__device__ bf16 g_ph[64UL * 1024 * 1024], g_pl[64UL * 1024 * 1024];
__device__ bf16 g_ch[8192UL * 4096], g_cl[8192UL * 4096];
__device__ float g_attn_fb[64UL * 1024 * 1024];

// ================= helpers =================
__device__ __forceinline__ uint32_t smem_u32(const void* p) {
    return (uint32_t)__cvta_generic_to_shared(p);
}
__device__ __forceinline__ void ldsm4(uint32_t* r, uint32_t a) {
    asm volatile("ldmatrix.sync.aligned.m8n8.x4.shared.b16 {%0,%1,%2,%3},[%4];\n"
        : "=r"(r[0]), "=r"(r[1]), "=r"(r[2]), "=r"(r[3]) : "r"(a));
}
__device__ __forceinline__ void mma_bf16(float* d, const uint32_t* a, const uint32_t* b) {
    asm("mma.sync.aligned.m16n8k16.row.col.f32.bf16.bf16.f32 "
        "{%0,%1,%2,%3},{%4,%5,%6,%7},{%8,%9},{%0,%1,%2,%3};\n"
        : "+f"(d[0]), "+f"(d[1]), "+f"(d[2]), "+f"(d[3])
        : "r"(a[0]), "r"(a[1]), "r"(a[2]), "r"(a[3]), "r"(b[0]), "r"(b[1]));
}
__device__ __forceinline__ void cpasync16(uint32_t dst, const void* src) {
    asm volatile("cp.async.cg.shared.global [%0], [%1], 16;" :: "r"(dst), "l"(src));
}
#define CP_COMMIT() asm volatile("cp.async.commit_group;" ::: "memory")
#define CP_WAIT1()  asm volatile("cp.async.wait_group 1;" ::: "memory")

__device__ __forceinline__ void split_bf16(float x, bf16& h, bf16& l) {
    h = __float2bfloat16(x);
    l = __float2bfloat16(x - __bfloat162float(h));
}

// ================= bf16x3 cp.async pipelined GEMM =================
// Block tile 128x128x32, 4 warps (128 thr) in 2x2 grid of 64x64 warp tiles.
// 2-stage pipeline, 2 CTAs/SM. Stage: Ah/Al/Bh/Bl each 128*80 B.
#define STAGE_BYTES 40960
#define SMEM_GEMM   81920

__device__ __forceinline__ void load_stage(
    uint32_t sbase, const bf16* __restrict__ Ah, const bf16* __restrict__ Al, int lda,
    const bf16* __restrict__ Bh, const bf16* __restrict__ Bl, int ldb,
    int m0, int n0, int k0)
{
    const int tid = threadIdx.x;     // 128 threads
#pragma unroll
    for (int i = 0; i < 4; i++) {
        const int chunk = tid + i * 128;       // 512 chunks: 128 rows x 4
        const int row = chunk >> 2;
        const int cb  = (chunk & 3) * 16;
        const int ce  = (chunk & 3) * 8;
        const uint32_t so = sbase + row * 80 + cb;
        cpasync16(so,          Ah + (size_t)(m0 + row) * lda + k0 + ce);
        cpasync16(so + 10240,  Al + (size_t)(m0 + row) * lda + k0 + ce);
        cpasync16(so + 20480,  Bh + (size_t)(n0 + row) * ldb + k0 + ce);
        cpasync16(so + 30720,  Bl + (size_t)(n0 + row) * ldb + k0 + ce);
    }
}

template <int OUTMODE /*0=f32, 1=bf16 hi/lo*/, bool BIAS>
__device__ __forceinline__ void gemm_core(
    const bf16* __restrict__ Ah, const bf16* __restrict__ Al, int lda,
    const bf16* __restrict__ Bh, const bf16* __restrict__ Bl, int ldb,
    float* __restrict__ C, bf16* __restrict__ Ch, bf16* __restrict__ Cl, int ldc,
    int K, const float* __restrict__ bias)
{
    extern __shared__ char smem[];
    const uint32_t sb = smem_u32(smem);
    const int tid = threadIdx.x, lane = tid & 31, warp = tid >> 5;
    const int wm = warp >> 1, wn = warp & 1;       // 2x2 warp grid, 64x64 tiles
    const int m0 = blockIdx.y * 128, n0 = blockIdx.x * 128;

    float acc[4][8][4] = {};   // [m16][n8][regs]

    load_stage(sb,               Ah, Al, lda, Bh, Bl, ldb, m0, n0, 0);
    CP_COMMIT();
    load_stage(sb + STAGE_BYTES, Ah, Al, lda, Bh, Bl, ldb, m0, n0, 32);
    CP_COMMIT();

    const int T = K >> 5;
    const int offA = (lane & 15) * 80 + (lane >> 4) * 16;
    const int offB = (((lane >> 4) & 1) * 8 + (lane & 7)) * 80 + ((lane >> 3) & 1) * 16;

    for (int t = 0; t < T; t++) {
        CP_WAIT1();
        __syncthreads();
        const uint32_t st = sb + (t & 1) * STAGE_BYTES;
        const uint32_t baseAh = st + wm * 64 * 80 + offA;
        const uint32_t baseAl = baseAh + 10240;
        const uint32_t baseBh = st + 20480 + wn * 64 * 80 + offB;
        const uint32_t baseBl = baseBh + 10240;

#pragma unroll
        for (int ks = 0; ks < 2; ks++) {
            uint32_t bh[4][4], bl[4][4], af[4][4];
#pragma unroll
            for (int j = 0; j < 4; j++) {
                ldsm4(bh[j], baseBh + j * 16 * 80 + ks * 32);
                ldsm4(bl[j], baseBl + j * 16 * 80 + ks * 32);
            }
#pragma unroll
            for (int mi = 0; mi < 4; mi++)
                ldsm4(af[mi], baseAh + mi * 16 * 80 + ks * 32);

            // sweep 1: hi*hi
#pragma unroll
            for (int mi = 0; mi < 4; mi++)
#pragma unroll
                for (int ni = 0; ni < 8; ni++)
                    mma_bf16(acc[mi][ni], af[mi], &bh[ni >> 1][(ni & 1) * 2]);
            // sweep 2: hi*lo
#pragma unroll
            for (int mi = 0; mi < 4; mi++)
#pragma unroll
                for (int ni = 0; ni < 8; ni++)
                    mma_bf16(acc[mi][ni], af[mi], &bl[ni >> 1][(ni & 1) * 2]);
            // reload A-lo into same frags; sweep 3: lo*hi
#pragma unroll
            for (int mi = 0; mi < 4; mi++)
                ldsm4(af[mi], baseAl + mi * 16 * 80 + ks * 32);
#pragma unroll
            for (int mi = 0; mi < 4; mi++)
#pragma unroll
                for (int ni = 0; ni < 8; ni++)
                    mma_bf16(acc[mi][ni], af[mi], &bh[ni >> 1][(ni & 1) * 2]);
        }
        __syncthreads();
        if (t + 2 < T)
            load_stage(sb + (t & 1) * STAGE_BYTES, Ah, Al, lda, Bh, Bl, ldb,
                       m0, n0, (t + 2) * 32);
        CP_COMMIT();
    }

    const int mw = m0 + wm * 64, nw = n0 + wn * 64;
#pragma unroll
    for (int mi = 0; mi < 4; mi++) {
        const int r0 = mw + mi * 16 + (lane >> 2);
#pragma unroll
        for (int ni = 0; ni < 8; ni++) {
            const int c = nw + ni * 8 + (lane & 3) * 2;
            float v0 = acc[mi][ni][0], v1 = acc[mi][ni][1];
            float v2 = acc[mi][ni][2], v3 = acc[mi][ni][3];
            if (BIAS) {
                float2 bb = *reinterpret_cast<const float2*>(&bias[c]);
                v0 += bb.x; v1 += bb.y; v2 += bb.x; v3 += bb.y;
            }
            if (OUTMODE == 0) {
                float2 o0; o0.x = v0; o0.y = v1;
                float2 o1; o1.x = v2; o1.y = v3;
                *reinterpret_cast<float2*>(&C[(size_t)r0 * ldc + c]) = o0;
                *reinterpret_cast<float2*>(&C[(size_t)(r0 + 8) * ldc + c]) = o1;
            } else {
                bf16 h, l;
                __nv_bfloat162 hh, ll;
                split_bf16(v0, h, l); hh.x = h; ll.x = l;
                split_bf16(v1, h, l); hh.y = h; ll.y = l;
                *reinterpret_cast<__nv_bfloat162*>(&Ch[(size_t)r0 * ldc + c]) = hh;
                *reinterpret_cast<__nv_bfloat162*>(&Cl[(size_t)r0 * ldc + c]) = ll;
                split_bf16(v2, h, l); hh.x = h; ll.x = l;
                split_bf16(v3, h, l); hh.y = h; ll.y = l;
                *reinterpret_cast<__nv_bfloat162*>(&Ch[(size_t)(r0 + 8) * ldc + c]) = hh;
                *reinterpret_cast<__nv_bfloat162*>(&Cl[(size_t)(r0 + 8) * ldc + c]) = ll;
            }
        }
    }
}

// ---------------- GEMM wrappers ----------------
__global__ __launch_bounds__(128, 2) void gemm_proj3_kernel(
    const bf16* xh, const bf16* xl, const bf16* wth, const bf16* wtl,
    bf16* qh, bf16* ql, bf16* kh, bf16* kl, bf16* vh, bf16* vl,
    const float* bq, const float* bk, const float* bv)
{
    const int z = blockIdx.z;
    const size_t xo = (size_t)z * 8192 * 512;
    const size_t wo_ = (size_t)z * 4096 * 512;
    bf16* Ch = (z == 0) ? qh : (z == 1) ? kh : vh;
    bf16* Cl = (z == 0) ? ql : (z == 1) ? kl : vl;
    const float* bias = (z == 0) ? bq : (z == 1) ? bk : bv;
    gemm_core<1, true>(xh + xo, xl + xo, 512, wth + wo_, wtl + wo_, 512,
                       nullptr, Ch, Cl, 4096, 512, bias);
}

__global__ __launch_bounds__(128, 2) void gemm_qk_kernel(
    const bf16* Qh, const bf16* Ql, const bf16* Kh, const bf16* Kl, float* logits)
{
    const int z = blockIdx.z, b = z >> 3, h = z & 7;
    const size_t ao = (size_t)b * 1024 * 4096 + (size_t)h * 512;
    gemm_core<0, false>(Qh + ao, Ql + ao, 4096, Kh + ao, Kl + ao, 4096,
                        logits + ((size_t)z << 20), nullptr, nullptr, 1024, 512, nullptr);
}

__global__ __launch_bounds__(128, 2) void gemm_av_kernel(
    const bf16* Ph, const bf16* Pl, const bf16* VTh, const bf16* VTl,
    bf16* Ch, bf16* Cl)
{
    const int z = blockIdx.z, b = z >> 3, h = z & 7;
    const size_t po = (size_t)z << 20;
    const size_t vo = (size_t)z * 512 * 1024;
    const size_t co = (size_t)b * 1024 * 4096 + (size_t)h * 512;
    gemm_core<1, false>(Ph + po, Pl + po, 1024, VTh + vo, VTl + vo, 1024,
                        nullptr, Ch + co, Cl + co, 4096, 1024, nullptr);
}

__global__ __launch_bounds__(128, 2) void gemm_wo_kernel(
    const bf16* Ah, const bf16* Al, const bf16* Wth, const bf16* Wtl,
    float* out, const float* bo)
{
    gemm_core<0, true>(Ah, Al, 4096, Wth, Wtl, 4096, out, nullptr, nullptr, 512, 4096, bo);
}

// ---------------- prep kernels ----------------
__global__ __launch_bounds__(256) void split3_kernel(
    const float* __restrict__ q_ip, const float* __restrict__ k_ip,
    const float* __restrict__ v_ip, bf16* __restrict__ xh, bf16* __restrict__ xl)
{
    const int z = blockIdx.y;
    const float* src = (z == 0) ? q_ip : (z == 1) ? k_ip : v_ip;
    bf16* dh = xh + (size_t)z * 8192 * 512;
    bf16* dl = xl + (size_t)z * 8192 * 512;
    const int base = blockIdx.x * 1024 + threadIdx.x;

    float4 v[4];
#pragma unroll
    for (int j = 0; j < 4; j++)
        v[j] = reinterpret_cast<const float4*>(src)[base + j * 256];
#pragma unroll
    for (int j = 0; j < 4; j++) {
        const int i = base + j * 256;
        bf16 h0, l0, h1, l1, h2, l2, h3, l3;
        split_bf16(v[j].x, h0, l0); split_bf16(v[j].y, h1, l1);
        split_bf16(v[j].z, h2, l2); split_bf16(v[j].w, h3, l3);
        __nv_bfloat162 a, b2;
        a.x = h0; a.y = h1; b2.x = h2; b2.y = h3;
        reinterpret_cast<__nv_bfloat162*>(dh)[2 * i]     = a;
        reinterpret_cast<__nv_bfloat162*>(dh)[2 * i + 1] = b2;
        a.x = l0; a.y = l1; b2.x = l2; b2.y = l3;
        reinterpret_cast<__nv_bfloat162*>(dl)[2 * i]     = a;
        reinterpret_cast<__nv_bfloat162*>(dl)[2 * i + 1] = b2;
    }
}

__global__ __launch_bounds__(256) void tsplit_kernel(
    const float* __restrict__ src, bf16* __restrict__ th, bf16* __restrict__ tl,
    int R0, int C0)
{
    __shared__ float tile[32][33];
    const int c0 = blockIdx.x * 32, r0 = blockIdx.y * 32;
    const int tx = threadIdx.x & 31, ty0 = threadIdx.x >> 5;
#pragma unroll
    for (int j = 0; j < 4; j++) {
        const int ty = ty0 * 4 + j;
        tile[ty][tx] = src[(size_t)(r0 + ty) * C0 + c0 + tx];
    }
    __syncthreads();
#pragma unroll
    for (int j = 0; j < 4; j++) {
        const int ty = ty0 * 4 + j;
        float v = tile[tx][ty];
        bf16 h, l; split_bf16(v, h, l);
        th[(size_t)(c0 + ty) * R0 + r0 + tx] = h;
        tl[(size_t)(c0 + ty) * R0 + r0 + tx] = l;
    }
}

__global__ __launch_bounds__(256) void tsplit3_kernel(
    const float* __restrict__ wq, const float* __restrict__ wk,
    const float* __restrict__ wv, bf16* __restrict__ wth, bf16* __restrict__ wtl)
{
    const int z = blockIdx.z;
    const float* src = (z == 0) ? wq : (z == 1) ? wk : wv;
    bf16* th = wth + (size_t)z * 4096 * 512;
    bf16* tl = wtl + (size_t)z * 4096 * 512;
    __shared__ float tile[32][33];
    const int c0 = blockIdx.x * 32, r0 = blockIdx.y * 32;
    const int tx = threadIdx.x & 31, ty0 = threadIdx.x >> 5;
#pragma unroll
    for (int j = 0; j < 4; j++) {
        const int ty = ty0 * 4 + j;
        tile[ty][tx] = src[(size_t)(r0 + ty) * 4096 + c0 + tx];
    }
    __syncthreads();
#pragma unroll
    for (int j = 0; j < 4; j++) {
        const int ty = ty0 * 4 + j;
        float v = tile[tx][ty];
        bf16 h, l; split_bf16(v, h, l);
        th[(size_t)(c0 + ty) * 512 + r0 + tx] = h;
        tl[(size_t)(c0 + ty) * 512 + r0 + tx] = l;
    }
}

__global__ __launch_bounds__(256) void vtrans_kernel(
    const bf16* __restrict__ Vh, const bf16* __restrict__ Vl,
    bf16* __restrict__ VTh, bf16* __restrict__ VTl)
{
    const int z = blockIdx.z, b = z >> 3, h = z & 7;
    const int s0 = blockIdx.x * 32, d0 = blockIdx.y * 32;
    __shared__ bf16 th[32][33], tl2[32][33];
    const int tx = threadIdx.x & 31, ty0 = threadIdx.x >> 5;
    const size_t srcb = (size_t)(b * 1024) * 4096 + (size_t)h * 512;
#pragma unroll
    for (int j = 0; j < 4; j++) {
        const int ty = ty0 * 4 + j;
        th[ty][tx]  = Vh[srcb + (size_t)(s0 + ty) * 4096 + d0 + tx];
        tl2[ty][tx] = Vl[srcb + (size_t)(s0 + ty) * 4096 + d0 + tx];
    }
    __syncthreads();
    const size_t dstb = (size_t)z * 512 * 1024;
#pragma unroll
    for (int j = 0; j < 4; j++) {
        const int ty = ty0 * 4 + j;
        VTh[dstb + (size_t)(d0 + ty) * 1024 + s0 + tx] = th[tx][ty];
        VTl[dstb + (size_t)(d0 + ty) * 1024 + s0 + tx] = tl2[tx][ty];
    }
}

// ---------------- masked softmax: warp-per-row ----------------
__global__ __launch_bounds__(256) void softmax_kernel(
    float* __restrict__ attn, const float* __restrict__ mask,
    bf16* __restrict__ Ph, bf16* __restrict__ Pl)
{
    const int wid = threadIdx.x >> 5, lane = threadIdx.x & 31;
    const int r = blockIdx.x * 8 + wid;
    const int q = r & 1023;
    const int b = r >> 13;
    float* row = attn + (size_t)r * 1024;
    const float* mrow = mask + ((size_t)b * 1024 + q) * 1024;
    const float scale = 0.044194173824159216f;

    float4 v[8];
#pragma unroll
    for (int j = 0; j < 8; j++) {
        const int c4 = lane + j * 32;
        float4 lg = *reinterpret_cast<const float4*>(&row[c4 * 4]);
        float4 mk = *reinterpret_cast<const float4*>(&mrow[c4 * 4]);
        v[j].x = lg.x * scale + mk.x * (-1e9f);
        v[j].y = lg.y * scale + mk.y * (-1e9f);
        v[j].z = lg.z * scale + mk.z * (-1e9f);
        v[j].w = lg.w * scale + mk.w * (-1e9f);
    }

    float mx = -INFINITY;
#pragma unroll
    for (int j = 0; j < 8; j++)
        mx = fmaxf(mx, fmaxf(fmaxf(v[j].x, v[j].y), fmaxf(v[j].z, v[j].w)));
#pragma unroll
    for (int o = 16; o > 0; o >>= 1)
        mx = fmaxf(mx, __shfl_xor_sync(0xffffffffu, mx, o));

    float s = 0.f;
#pragma unroll
    for (int j = 0; j < 8; j++) {
        v[j].x = __expf(v[j].x - mx); v[j].y = __expf(v[j].y - mx);
        v[j].z = __expf(v[j].z - mx); v[j].w = __expf(v[j].w - mx);
        s += (v[j].x + v[j].y) + (v[j].z + v[j].w);
    }
#pragma unroll
    for (int o = 16; o > 0; o >>= 1)
        s += __shfl_xor_sync(0xffffffffu, s, o);
    const float inv = 1.0f / s;

    const size_t pbase = (size_t)r * 1024;
#pragma unroll
    for (int j = 0; j < 8; j++) {
        const int c4 = lane + j * 32;
        v[j].x *= inv; v[j].y *= inv; v[j].z *= inv; v[j].w *= inv;
        *reinterpret_cast<float4*>(&row[c4 * 4]) = v[j];

        bf16 h0, l0, h1, l1, h2, l2, h3, l3;
        split_bf16(v[j].x, h0, l0); split_bf16(v[j].y, h1, l1);
        split_bf16(v[j].z, h2, l2); split_bf16(v[j].w, h3, l3);
        __nv_bfloat162 hv[2], lv[2];
        hv[0].x = h0; hv[0].y = h1; hv[1].x = h2; hv[1].y = h3;
        lv[0].x = l0; lv[0].y = l1; lv[1].x = l2; lv[1].y = l3;
        *reinterpret_cast<uint2*>(&Ph[pbase + c4 * 4]) = *reinterpret_cast<uint2*>(hv);
        *reinterpret_cast<uint2*>(&Pl[pbase + c4 * 4]) = *reinterpret_cast<uint2*>(lv);
    }
}

// ===========================================================================
extern "C" void kernel_launch(void* const* d_in, const int* in_sizes, int n_in,
                              void* d_out, int out_size)
{
    const float* v_ip = (const float*)d_in[0];
    const float* k_ip = (const float*)d_in[1];
    const float* q_ip = (const float*)d_in[2];
    const float* mask = (const float*)d_in[3];
    const float* wq   = (const float*)d_in[4];
    const float* bq   = (const float*)d_in[5];
    const float* wk   = (const float*)d_in[6];
    const float* bk   = (const float*)d_in[7];
    const float* wv   = (const float*)d_in[8];
    const float* bv   = (const float*)d_in[9];
    const float* wo   = (const float*)d_in[10];
    const float* bo   = (const float*)d_in[11];

    bf16 *xh, *xl, *wth, *wtl, *qh, *ql, *kh, *kl, *vh, *vl, *vth, *vtl, *ph, *pl, *ch, *cl;
    float* fb;
    cudaGetSymbolAddress((void**)&xh, g_xh);   cudaGetSymbolAddress((void**)&xl, g_xl);
    cudaGetSymbolAddress((void**)&wth, g_wth); cudaGetSymbolAddress((void**)&wtl, g_wtl);
    cudaGetSymbolAddress((void**)&qh, g_qh);   cudaGetSymbolAddress((void**)&ql, g_ql);
    cudaGetSymbolAddress((void**)&kh, g_kh);   cudaGetSymbolAddress((void**)&kl, g_kl);
    cudaGetSymbolAddress((void**)&vh, g_vh);   cudaGetSymbolAddress((void**)&vl, g_vl);
    cudaGetSymbolAddress((void**)&vth, g_vth); cudaGetSymbolAddress((void**)&vtl, g_vtl);
    cudaGetSymbolAddress((void**)&ph, g_ph);   cudaGetSymbolAddress((void**)&pl, g_pl);
    cudaGetSymbolAddress((void**)&ch, g_ch);   cudaGetSymbolAddress((void**)&cl, g_cl);
    cudaGetSymbolAddress((void**)&fb, g_attn_fb);

    cudaFuncSetAttribute(gemm_proj3_kernel, cudaFuncAttributeMaxDynamicSharedMemorySize, SMEM_GEMM);
    cudaFuncSetAttribute(gemm_qk_kernel,    cudaFuncAttributeMaxDynamicSharedMemorySize, SMEM_GEMM);
    cudaFuncSetAttribute(gemm_av_kernel,    cudaFuncAttributeMaxDynamicSharedMemorySize, SMEM_GEMM);
    cudaFuncSetAttribute(gemm_wo_kernel,    cudaFuncAttributeMaxDynamicSharedMemorySize, SMEM_GEMM);

    const size_t OUT_ELEMS  = 8UL * 1024 * 512;
    const size_t ATTN_ELEMS = 64UL * 1024 * 1024;
    float* out  = (float*)d_out;
    float* attn = ((size_t)out_size >= OUT_ELEMS + ATTN_ELEMS) ? (out + OUT_ELEMS) : fb;

    // 1) prep
    split3_kernel<<<dim3(1024, 3), 256>>>(q_ip, k_ip, v_ip, xh, xl);
    tsplit3_kernel<<<dim3(128, 16, 3), 256>>>(wq, wk, wv, wth, wtl);

    // 2) Q/K/V projections (N=4096 -> 32 tiles of 128)
    gemm_proj3_kernel<<<dim3(32, 64, 3), 128, SMEM_GEMM>>>(
        xh, xl, wth, wtl, qh, ql, kh, kl, vh, vl, bq, bk, bv);

    // 3) V^T per (b,h)
    vtrans_kernel<<<dim3(32, 16, 64), 256>>>(vh, vl, vth, vtl);

    // 4) logits = Q K^T (N=1024 -> 8 tiles)
    gemm_qk_kernel<<<dim3(8, 8, 64), 128, SMEM_GEMM>>>(qh, ql, kh, kl, attn);

    // 5) masked softmax -> attn fp32 + P bf16 hi/lo
    softmax_kernel<<<8192, 256>>>(attn, mask, ph, pl);

    // 6) ctx = P @ V (N=512 -> 4 tiles)
    gemm_av_kernel<<<dim3(4, 8, 64), 128, SMEM_GEMM>>>(ph, pl, vth, vtl, ch, cl);

    // 7) out = ctx @ wo + bo (N=512 -> 4 tiles of 128)
    tsplit_kernel<<<dim3(16, 128), 256>>>(wo, wth, wtl, 4096, 512);
    gemm_wo_kernel<<<dim3(4, 64), 128, SMEM_GEMM>>>(ch, cl, wth, wtl, out, bo);
}